// round 15
// baseline (speedup 1.0000x reference)
#include <cuda_runtime.h>
#include <cstdint>

#define DL 21
#define SS 512
#define HW (SS*SS)
#define NB 4
#define NE (NB*DL*HW)   // 22,020,096 (~84 MB fp32)

typedef unsigned long long u64;
__device__ __forceinline__ u64 f2u(float x, float y) {
    u64 r; asm("mov.b64 %0, {%1, %2};" : "=l"(r) : "f"(x), "f"(y)); return r;
}
__device__ __forceinline__ float2 u2f(u64 v) {
    float2 r; asm("mov.b64 {%0, %1}, %2;" : "=f"(r.x), "=f"(r.y) : "l"(v)); return r;
}
__device__ __forceinline__ u64 ffma2u(u64 a, u64 b, u64 c) {
    u64 d; asm("fma.rn.f32x2 %0, %1, %2, %3;" : "=l"(d) : "l"(a), "l"(b), "l"(c)); return d;
}

// ew planes for dirs 0/1, spatially transposed: [x][y]
__device__ __align__(16) float g_ewT[NB*2*HW];
// Label-innermost unary: (b, p'=x*512+y, l)   (+pad: lanes may read l0+2 dummy)
__device__ __align__(16) float g_ux[NE + 64];
// Directional results, label-innermost, p = y*512+x (y-major). o2 carries -3u.
__device__ __align__(16) float g_o0[NE + 64];
__device__ __align__(16) float g_o1[NE + 64];
__device__ __align__(16) float g_o2[NE + 64];
__device__ __align__(16) float g_o3[NE + 64];

// ---------------------------------------------------------------------------
// Fused transpose: g_ux[(b, x*512+y, l)] = u[b, l, y, x]
__global__ void __launch_bounds__(256)
ufuse(const float* __restrict__ u) {
    __shared__ float tile[8 * 693];           // yy*693 + l*33 + x  (22.2 KB)
    const int blk = blockIdx.x;               // 1024 = 4 b x 256 tiles
    const int b  = blk >> 8;
    const int t  = blk & 255;
    const int y0 = (t >> 4) << 5;
    const int x0 = (t & 15) << 5;

    for (int sc = 0; sc < 4; sc++) {
        if (sc) __syncthreads();
        for (int j = threadIdx.x; j < DL * 8 * 32; j += 256) {
            const int l  = j >> 8;
            const int yy = (j >> 5) & 7;
            const int xx = j & 31;
            tile[yy * 693 + l * 33 + xx] =
                u[((size_t)(b * DL + l) * SS + (y0 + (sc << 3) + yy)) * SS + x0 + xx];
        }
        __syncthreads();
        for (int j = threadIdx.x; j < 32 * 168; j += 256) {
            const int x = j / 168;
            const int r = j - x * 168;
            const int yy = r / DL;
            const int l  = r - yy * DL;
            g_ux[((size_t)b * HW + (size_t)(x0 + x) * SS + y0 + (sc << 3)) * DL + r]
                = tile[yy * 693 + l * 33 + x];
        }
    }
}

// ---------------------------------------------------------------------------
// 32x32 tile transpose (ew planes for dirs 0/1 only)
__global__ void __launch_bounds__(256)
transpose_ew(const float* __restrict__ ew) {
    __shared__ float tile[32][33];
    const int p  = blockIdx.x >> 8;           // 0..7 : b*2+d
    const int tt = blockIdx.x & 255;
    const int b = p >> 1, d = p & 1;
    const float* sp = ew + (size_t)(b * 4 + d) * HW;
    float* dp = g_ewT + (size_t)p * HW;
    const int ty0 = (tt >> 4) << 5;
    const int tx0 = (tt & 15) << 5;
    const int r  = threadIdx.x >> 3;
    const int q4 = (threadIdx.x & 7) << 2;
    float4 v = *reinterpret_cast<const float4*>(sp + (size_t)(ty0 + r) * SS + tx0 + q4);
    tile[r][q4 + 0] = v.x; tile[r][q4 + 1] = v.y;
    tile[r][q4 + 2] = v.z; tile[r][q4 + 3] = v.w;
    __syncthreads();
    float4 o = make_float4(tile[q4 + 0][r], tile[q4 + 1][r],
                           tile[q4 + 2][r], tile[q4 + 3][r]);
    *reinterpret_cast<float4*>(dp + (size_t)(tx0 + r) * SS + ty0 + q4) = o;
}

// ---------------------------------------------------------------------------
// Sweep: warp = 4 columns x 8 label-split threads. Thread (col, s) owns
// output labels: s<5 -> {3s,3s+1,3s+2}; s=5/6/7 -> {15,16}/{17,18}/{19,20}.
// Exchange = 21 shfl per step; candidates packed across k-pairs with
// fma.rn.f32x2 (63 -> 33 FMA issue slots). Zero barriers.
template<int DIR>
__device__ __forceinline__ void run_sweep(const float* __restrict__ ew,
                                          int b, int col, int l0, bool full3,
                                          int baseLane,
                                          const u64 (&Vp0)[11],
                                          const u64 (&Vp1)[11],
                                          const u64 (&Vp2)[11]) {
    const unsigned FM = 0xffffffffu;
    const float* ux = g_ux + (size_t)b * HW * DL;
    float* dst = ((DIR == 0) ? g_o0 : (DIR == 1) ? g_o1 : (DIR == 2) ? g_o2 : g_o3)
                 + (size_t)b * HW * DL;
    const float* warr;
    int ridx, rstr, sidx, sstr, widx, wstr;
    if (DIR == 0) {        // L->R: chain y=col, t=x; read (x*512+col), store (col*512+x)
        ridx = col * DL + l0;                 rstr =  SS * DL;
        sidx = (col * SS) * DL + l0;          sstr =  DL;
        warr = g_ewT + (size_t)(b * 2 + 0) * HW; widx = col;              wstr =  SS;
    } else if (DIR == 1) { // R->L
        ridx = ((SS-1) * SS + col) * DL + l0; rstr = -SS * DL;
        sidx = (col * SS + SS - 1) * DL + l0; sstr = -DL;
        warr = g_ewT + (size_t)(b * 2 + 1) * HW; widx = (SS-1)*SS + col;  wstr = -SS;
    } else if (DIR == 2) { // T->D: chain x=col, t=y; read (col*512+y), store (y*512+col)
        ridx = (col * SS) * DL + l0;          rstr =  DL;
        sidx = col * DL + l0;                 sstr =  SS * DL;
        warr = ew + (size_t)(b * 4 + 2) * HW;    widx = col;              wstr =  SS;
    } else {               // B->U
        ridx = (col * SS + SS - 1) * DL + l0; rstr = -DL;
        sidx = ((SS-1) * SS + col) * DL + l0; sstr = -SS * DL;
        warr = ew + (size_t)(b * 4 + 3) * HW;    widx = (SS-1)*SS + col;  wstr = -SS;
    }

    float L0, L1, L2;
    {   // t = 0 border: L = u
        float u0 = __ldg(ux + ridx), u1 = __ldg(ux + ridx + 1), u2 = __ldg(ux + ridx + 2);
        L0 = u0; L1 = u1; L2 = u2;
        if (DIR == 2) {
            dst[sidx]     = fmaf(-3.0f, u0, L0);
            dst[sidx + 1] = fmaf(-3.0f, u1, L1);
            if (full3) dst[sidx + 2] = fmaf(-3.0f, u2, L2);
        } else {
            dst[sidx] = L0; dst[sidx + 1] = L1;
            if (full3) dst[sidx + 2] = L2;
        }
    }
    // depth-2 prefetch
    int rp = ridx + rstr, wp = widx + wstr;
    float au0 = __ldg(ux + rp), au1 = __ldg(ux + rp + 1), au2 = __ldg(ux + rp + 2);
    float aw  = __ldg(warr + wp);
    rp += rstr; wp += wstr;
    float bu0 = __ldg(ux + rp), bu1 = __ldg(ux + rp + 1), bu2 = __ldg(ux + rp + 2);
    float bw  = __ldg(warr + wp);

    auto step = [&](float u0, float u1, float u2, float w, int so) {
        const float P0 = L0, P1 = L1, P2 = L2;
        const u64 w2 = f2u(w, w);
        float m0a, m0b, m1a, m1b, m2a, m2b;
#pragma unroll
        for (int kk = 0; kk < 11; kk++) {
            const int k0 = 2 * kk, k1 = 2 * kk + 1;
            // fetch L[k0], L[k1] via shfl; pad odd slot with huge value
            const int q0 = (k0 < 15) ? k0 / 3 : 5 + (k0 - 15) / 2;
            const int s0 = (k0 < 15) ? k0 % 3 : (k0 - 15) & 1;
            const float A = __shfl_sync(FM, s0 == 0 ? P0 : (s0 == 1 ? P1 : P2),
                                        baseLane | q0);
            float B;
            if (k1 < DL) {
                const int q1 = (k1 < 15) ? k1 / 3 : 5 + (k1 - 15) / 2;
                const int s1 = (k1 < 15) ? k1 % 3 : (k1 - 15) & 1;
                B = __shfl_sync(FM, s1 == 0 ? P0 : (s1 == 1 ? P1 : P2),
                                baseLane | q1);
            } else {
                B = 1e30f;                     // padded candidate: never the min
            }
            const u64 Lp = f2u(A, B);
            const float2 c0 = u2f(ffma2u(w2, Vp0[kk], Lp));
            const float2 c1 = u2f(ffma2u(w2, Vp1[kk], Lp));
            const float2 c2 = u2f(ffma2u(w2, Vp2[kk], Lp));
            if (kk == 0) {
                m0a = c0.x; m0b = c0.y;
                m1a = c1.x; m1b = c1.y;
                m2a = c2.x; m2b = c2.y;
            } else {
                m0a = fminf(m0a, c0.x); m0b = fminf(m0b, c0.y);
                m1a = fminf(m1a, c1.x); m1b = fminf(m1b, c1.y);
                m2a = fminf(m2a, c2.x); m2b = fminf(m2b, c2.y);
            }
        }
        L0 = u0 + fminf(m0a, m0b);
        L1 = u1 + fminf(m1a, m1b);
        L2 = u2 + fminf(m2a, m2b);
        if (DIR == 2) {
            dst[so]     = fmaf(-3.0f, u0, L0);
            dst[so + 1] = fmaf(-3.0f, u1, L1);
            if (full3) dst[so + 2] = fmaf(-3.0f, u2, L2);
        } else {
            dst[so] = L0; dst[so + 1] = L1;
            if (full3) dst[so + 2] = L2;
        }
    };

    int sp = sidx;
#pragma unroll 1
    for (int t = 1; t <= SS - 3; t++) {
        rp += rstr; wp += wstr;
        float nu0 = __ldg(ux + rp), nu1 = __ldg(ux + rp + 1), nu2 = __ldg(ux + rp + 2);
        float nw  = __ldg(warr + wp);
        sp += sstr;
        step(au0, au1, au2, aw, sp);
        au0 = bu0; au1 = bu1; au2 = bu2; aw = bw;
        bu0 = nu0; bu1 = nu1; bu2 = nu2; bw = nw;
    }
    sp += sstr; step(au0, au1, au2, aw, sp);
    sp += sstr; step(bu0, bu1, bu2, bw, sp);
}

__global__ void __launch_bounds__(64, 8)
sweep(const float* __restrict__ ew, const float* __restrict__ lc) {
    const int bx   = blockIdx.x;              // 1024 blocks x 2 warps
    const int dir  = bx >> 8;
    const int b    = (bx >> 6) & 3;
    const int cg   = bx & 63;
    const int lane = threadIdx.x & 31;
    const int s    = lane & 7;
    const int col  = (cg << 3) + ((threadIdx.x >> 5) << 2) + (lane >> 3);
    const bool full3 = (s < 5);
    const int l0 = full3 ? 3 * s : 15 + 2 * (s - 5);
    const int l1 = l0 + 1;
    const int l2 = full3 ? l0 + 2 : l1;      // dup for 2-label lanes (never sourced)
    const int baseLane = lane & 24;

    // V packed across k-pairs: Vpj[kk] = {V[2kk][lj], V[2kk+1][lj]} (pad 0)
    u64 Vp0[11], Vp1[11], Vp2[11];
#pragma unroll
    for (int kk = 0; kk < 11; kk++) {
        const int ka = 2 * kk, kb = 2 * kk + 1;
        const float a0 = __ldg(lc + ka * DL + l0);
        const float a1 = __ldg(lc + ka * DL + l1);
        const float a2 = __ldg(lc + ka * DL + l2);
        const float b0 = (kb < DL) ? __ldg(lc + kb * DL + l0) : 0.0f;
        const float b1 = (kb < DL) ? __ldg(lc + kb * DL + l1) : 0.0f;
        const float b2 = (kb < DL) ? __ldg(lc + kb * DL + l2) : 0.0f;
        Vp0[kk] = f2u(a0, b0);
        Vp1[kk] = f2u(a1, b1);
        Vp2[kk] = f2u(a2, b2);
    }

    if (dir == 0)      run_sweep<0>(ew, b, col, l0, full3, baseLane, Vp0, Vp1, Vp2);
    else if (dir == 1) run_sweep<1>(ew, b, col, l0, full3, baseLane, Vp0, Vp1, Vp2);
    else if (dir == 2) run_sweep<2>(ew, b, col, l0, full3, baseLane, Vp0, Vp1, Vp2);
    else               run_sweep<3>(ew, b, col, l0, full3, baseLane, Vp0, Vp1, Vp2);
}

// ---------------------------------------------------------------------------
// out[(b*21+l)*HW + p] = (o0+o1+o2+o3)[(b*HW+p)*21 + l]   (o2 carries -3u)
__global__ void __launch_bounds__(256)
combine(float* __restrict__ out) {
    __shared__ float tile[DL][132];
    const int blk = blockIdx.x;               // 8192
    const int b  = blk >> 11;
    const int p0 = (blk & 2047) << 7;
    const size_t ib = ((size_t)b * HW + p0) * DL;
    for (int j = threadIdx.x; j < (DL * 128) / 4; j += 256) {
        const int f = j << 2;
        float4 a  = *reinterpret_cast<const float4*>(g_o0 + ib + f);
        float4 b4 = *reinterpret_cast<const float4*>(g_o1 + ib + f);
        float4 c  = *reinterpret_cast<const float4*>(g_o2 + ib + f);
        float4 d  = *reinterpret_cast<const float4*>(g_o3 + ib + f);
        tile[(f + 0) % DL][(f + 0) / DL] = a.x + b4.x + c.x + d.x;
        tile[(f + 1) % DL][(f + 1) / DL] = a.y + b4.y + c.y + d.y;
        tile[(f + 2) % DL][(f + 2) / DL] = a.z + b4.z + c.z + d.z;
        tile[(f + 3) % DL][(f + 3) / DL] = a.w + b4.w + c.w + d.w;
    }
    __syncthreads();
    for (int j = threadIdx.x; j < DL * 32; j += 256) {
        const int l = j >> 5, i4 = (j & 31) << 2;
        float4 o = make_float4(tile[l][i4], tile[l][i4 + 1],
                               tile[l][i4 + 2], tile[l][i4 + 3]);
        *reinterpret_cast<float4*>(out + (size_t)(b * DL + l) * HW + p0 + i4) = o;
    }
}

// ---------------------------------------------------------------------------
extern "C" void kernel_launch(void* const* d_in, const int* in_sizes, int n_in,
                              void* d_out, int out_size) {
    const float* unary = (const float*)d_in[0];   // (4,1,21,512,512)
    const float* ew    = (const float*)d_in[1];   // (4,4,512,512)
    const float* lc    = (const float*)d_in[2];   // (21,21)
    float* out = (float*)d_out;                   // (4,1,21,512,512)

    ufuse<<<1024, 256>>>(unary);
    transpose_ew<<<NB * 2 * 256, 256>>>(ew);
    sweep<<<1024, 64>>>(ew, lc);
    combine<<<8192, 256>>>(out);
}